// round 4
// baseline (speedup 1.0000x reference)
#include <cuda_runtime.h>
#include <cuda_bf16.h>

// Capsule routing, factorized (u_hat never materialized), f32x2 packed FMA
// with pairing along the contiguous axis (natural LDS.128 b-operands).
// u (32,1024,256) f32; W (256,2048) f32; out (32,32,64) f32.

#define BB 32
#define II 1024
#define CC 256
#define NN 32
#define DD 64
#define ND 2048

#define ICH 4    // blog i-chunks (256 i each)
#define KSP 4    // blog c-splits (64 c each)
#define ISP 16   // sgemm i-splits (64 i each)

typedef unsigned long long ull;

__device__ float g_part[BB * 8 * CC];                 // colsum partials
__device__ float g_V[BB * NN * CC];                   // V[b][n][c]
__device__ float g_blogp[KSP * BB * NN * II];         // blog partials [ks][b][n][i]
__device__ float g_Spart[ISP * BB * NN * CC];         // S partials [isp][b][n][c]

// ---- f32x2 helpers -------------------------------------------------------
__device__ __forceinline__ ull pack2(float x) {
    ull r; unsigned xi = __float_as_uint(x);
    asm("mov.b64 %0, {%1, %1};" : "=l"(r) : "r"(xi));
    return r;
}
__device__ __forceinline__ void fma2(ull& d, ull a, ull b) {
    asm("fma.rn.f32x2 %0, %1, %2, %0;" : "+l"(d) : "l"(a), "l"(b));
}

// ---- colsum partials ----------------------------------------------------
__global__ void k_colsum_part(const float* __restrict__ u) {
    int q = blockIdx.x, b = blockIdx.y, c = threadIdx.x;
    const float* p = u + (size_t)b * II * CC + (size_t)q * 128 * CC + c;
    float s = 0.f;
#pragma unroll 8
    for (int i = 0; i < 128; i++) s += p[(size_t)i * CC];
    g_part[(b * 8 + q) * CC + c] = s;
}

// ---- blog: blog[b][n][i] += V[b][n][kslice] . u[b][i][kslice] -----------
// grid (ICH, KSP, BB), 256 thr. Block tile 32n x 256i, K=64.
// warp w -> n-quad {4w..4w+3}; lane -> i in {8*lane..8*lane+7} (4 f32x2 pairs).
__global__ __launch_bounds__(256, 3) void k_blog(const float* __restrict__ u) {
    __shared__ float sV[NN][68];       // V[n][kLocal 0..63]
    __shared__ float sU[16][260];      // u^T slice [kLocal16][i 256]
    int ich = blockIdx.x, ks = blockIdx.y, b = blockIdx.z;
    int i0 = ich * 256, kb = ks * 64;
    int t = threadIdx.x, lane = t & 31, w = t >> 5;

    // load V slice [32n][64c]
    {
        int n = t >> 3, c8 = t & 7;
        const float* vp = g_V + (size_t)(b * NN + n) * CC + kb + c8 * 8;
        float4 v0 = *(const float4*)vp, v1 = *(const float4*)(vp + 4);
        float* d = &sV[n][c8 * 8];
        d[0]=v0.x; d[1]=v0.y; d[2]=v0.z; d[3]=v0.w;
        d[4]=v1.x; d[5]=v1.y; d[6]=v1.z; d[7]=v1.w;
    }

    ull acc[4][4] = {};
#pragma unroll
    for (int s = 0; s < 4; s++) {
        // load u[i0+t][kb+s*16 .. +15] transposed into sU[k][i]
        const float* up = u + ((size_t)b * II + i0 + t) * CC + kb + s * 16;
        float4 a0 = *(const float4*)up, a1 = *(const float4*)(up + 4);
        float4 a2 = *(const float4*)(up + 8), a3 = *(const float4*)(up + 12);
        __syncthreads();
        sU[0][t]=a0.x; sU[1][t]=a0.y; sU[2][t]=a0.z; sU[3][t]=a0.w;
        sU[4][t]=a1.x; sU[5][t]=a1.y; sU[6][t]=a1.z; sU[7][t]=a1.w;
        sU[8][t]=a2.x; sU[9][t]=a2.y; sU[10][t]=a2.z; sU[11][t]=a2.w;
        sU[12][t]=a3.x; sU[13][t]=a3.y; sU[14][t]=a3.z; sU[15][t]=a3.w;
        __syncthreads();
#pragma unroll
        for (int k2 = 0; k2 < 16; k2++) {
            ull a[4];
#pragma unroll
            for (int j = 0; j < 4; j++) a[j] = pack2(sV[4 * w + j][s * 16 + k2]);
            const ull* pb = (const ull*)&sU[k2][8 * lane];
            ull b0 = pb[0], b1 = pb[1], b2 = pb[2], b3 = pb[3];
#pragma unroll
            for (int j = 0; j < 4; j++) {
                fma2(acc[j][0], a[j], b0);
                fma2(acc[j][1], a[j], b1);
                fma2(acc[j][2], a[j], b2);
                fma2(acc[j][3], a[j], b3);
            }
        }
    }
    // store partials
#pragma unroll
    for (int j = 0; j < 4; j++) {
        ull* op = (ull*)(g_blogp + (((size_t)ks * BB + b) * NN + 4 * w + j) * II + i0 + 8 * lane);
        op[0]=acc[j][0]; op[1]=acc[j][1]; op[2]=acc[j][2]; op[3]=acc[j][3];
    }
}

// ---- sgemm (+softmax prologue): S[n][c] += softmax_n(blog)[n][iwin] . u[iwin][c]
// grid (ISP, BB), 256 thr. Block tile 32n x 256c, K=64 i.
__global__ __launch_bounds__(256, 3) void k_sgemm(const float* __restrict__ u) {
    __shared__ float sC[NN][66];       // softmaxed coeffs [n][iLocal 0..63]
    __shared__ float sU[16][260];      // u slice [iLocal16][c 256]
    int isp = blockIdx.x, b = blockIdx.y;
    int i1 = isp * 64;
    int t = threadIdx.x, lane = t & 31, w = t >> 5;

    // prologue: sum 4 blog partials -> sC
    {
        int n = t >> 3, i8 = t & 7;
        float v[8] = {};
#pragma unroll
        for (int ks = 0; ks < KSP; ks++) {
            const float* p = g_blogp + (((size_t)ks * BB + b) * NN + n) * II + i1 + i8 * 8;
            float4 x0 = *(const float4*)p, x1 = *(const float4*)(p + 4);
            v[0]+=x0.x; v[1]+=x0.y; v[2]+=x0.z; v[3]+=x0.w;
            v[4]+=x1.x; v[5]+=x1.y; v[6]+=x1.z; v[7]+=x1.w;
        }
        float* d = &sC[n][i8 * 8];
#pragma unroll
        for (int j = 0; j < 8; j++) d[j] = v[j];
    }
    __syncthreads();
    // softmax over n, one column i per thread (t < 64)
    if (t < 64) {
        float vv[NN];
        float m = -1e30f;
#pragma unroll
        for (int n = 0; n < NN; n++) { vv[n] = sC[n][t]; m = fmaxf(m, vv[n]); }
        float s = 0.f;
#pragma unroll
        for (int n = 0; n < NN; n++) { vv[n] = __expf(vv[n] - m); s += vv[n]; }
        float inv = 1.0f / s;
#pragma unroll
        for (int n = 0; n < NN; n++) sC[n][t] = vv[n] * inv;
    }

    ull acc[4][4] = {};
#pragma unroll
    for (int s = 0; s < 4; s++) {
        // load u[i1 + s*16 + (t>>4)][(t&15)*16 ..] natural layout
        int il = t >> 4, c0 = (t & 15) * 16;
        const float* up = u + ((size_t)b * II + i1 + s * 16 + il) * CC + c0;
        float4 a0 = *(const float4*)up, a1 = *(const float4*)(up + 4);
        float4 a2 = *(const float4*)(up + 8), a3 = *(const float4*)(up + 12);
        __syncthreads();
        float* d = &sU[il][c0];
        *(float4*)d = a0; *(float4*)(d + 4) = a1;
        *(float4*)(d + 8) = a2; *(float4*)(d + 12) = a3;
        __syncthreads();
#pragma unroll
        for (int k2 = 0; k2 < 16; k2++) {
            ull a[4];
#pragma unroll
            for (int j = 0; j < 4; j++) a[j] = pack2(sC[4 * w + j][s * 16 + k2]);
            const ull* pb = (const ull*)&sU[k2][8 * lane];
            ull b0 = pb[0], b1 = pb[1], b2 = pb[2], b3 = pb[3];
#pragma unroll
            for (int j = 0; j < 4; j++) {
                fma2(acc[j][0], a[j], b0);
                fma2(acc[j][1], a[j], b1);
                fma2(acc[j][2], a[j], b2);
                fma2(acc[j][3], a[j], b3);
            }
        }
    }
#pragma unroll
    for (int j = 0; j < 4; j++) {
        ull* op = (ull*)(g_Spart + (((size_t)isp * BB + b) * NN + 4 * w + j) * CC + 8 * lane);
        op[0]=acc[j][0]; op[1]=acc[j][1]; op[2]=acc[j][2]; op[3]=acc[j][3];
    }
}

// ---- caps: out = squash(S @ W_n), V = out @ W_n^T -----------------------
// grid (n=32, bg=4), 256 thr, 8 b-rows per block. W_n slice in smem once.
#define CAPS_BL 8
#define CAPS_SM ((256 * 65 + CAPS_BL * 256 + CAPS_BL * 65) * 4)
__global__ __launch_bounds__(256, 1) void k_caps(const float* __restrict__ W,
                                                 int mode, float* __restrict__ dout) {
    extern __shared__ float sm[];
    float* sW = sm;                      // [256][65]
    float* sS = sm + 256 * 65;           // [8][256]
    float* sO = sS + CAPS_BL * 256;      // [8][65]
    int n = blockIdx.x, bg = blockIdx.y;
    int t = threadIdx.x, lane = t & 31, w = t >> 5;

#pragma unroll
    for (int r = 0; r < 32; r++) {
        int c = w + 8 * r;
        const float* wp = W + (size_t)c * ND + n * DD;
        sW[c * 65 + lane] = wp[lane];
        sW[c * 65 + lane + 32] = wp[lane + 32];
    }
#pragma unroll
    for (int bl = 0; bl < CAPS_BL; bl++) {
        int b = bg * CAPS_BL + bl;
        float s = 0.f;
        if (mode == 0) {
#pragma unroll
            for (int q = 0; q < 8; q++) s += g_part[(b * 8 + q) * CC + t];
            s *= (1.0f / 32.0f);
        } else {
#pragma unroll
            for (int q = 0; q < ISP; q++)
                s += g_Spart[(((size_t)q * BB + b) * NN + n) * CC + t];
        }
        sS[bl * CC + t] = s;
    }
    __syncthreads();

    // phase A: O[w][d] = sum_c S[w][c] W[c][d]  (warp w -> b-row w)
    float a0 = 0.f, a1 = 0.f;
    for (int k = 0; k < CC; k++) {
        float s = sS[w * CC + k];
        a0 += s * sW[k * 65 + lane];
        a1 += s * sW[k * 65 + lane + 32];
    }
    // squash
    float sq = a0 * a0 + a1 * a1;
#pragma unroll
    for (int off = 16; off; off >>= 1) sq += __shfl_xor_sync(0xffffffffu, sq, off);
    float f = rsqrtf(sq + 1e-7f);
    a0 *= f; a1 *= f;
    sO[w * 65 + lane] = a0; sO[w * 65 + lane + 32] = a1;
    if (mode == 2) {
        int b = bg * CAPS_BL + w;
        dout[(size_t)(b * NN + n) * DD + lane] = a0;
        dout[(size_t)(b * NN + n) * DD + lane + 32] = a1;
        return;
    }
    __syncthreads();

    // phase B: V[w][c] = sum_d O[w][d] W[c][d]
    float accB[8] = {};
    for (int k = 0; k < DD; k++) {
        float a = sO[w * 65 + k];
#pragma unroll
        for (int q = 0; q < 8; q++) accB[q] += a * sW[(lane + 32 * q) * 65 + k];
    }
    int b = bg * CAPS_BL + w;
#pragma unroll
    for (int q = 0; q < 8; q++)
        g_V[(size_t)(b * NN + n) * CC + lane + 32 * q] = accB[q];
}

// ---------------------------------------------------------------------------
extern "C" void kernel_launch(void* const* d_in, const int* in_sizes, int n_in,
                              void* d_out, int out_size) {
    const float* u = (const float*)d_in[0];
    const float* W = (const float*)d_in[1];
    if (n_in >= 2 && in_sizes[0] == CC * ND) {   // defensive order check
        u = (const float*)d_in[1];
        W = (const float*)d_in[0];
    }
    float* out = (float*)d_out;

    cudaFuncSetAttribute(k_caps, cudaFuncAttributeMaxDynamicSharedMemorySize, CAPS_SM);

    k_colsum_part<<<dim3(8, BB), 256>>>(u);
    k_caps<<<dim3(NN, BB / CAPS_BL), 256, CAPS_SM>>>(W, 0, nullptr);   // out0 -> V0

    for (int pass = 0; pass < 2; pass++) {
        k_blog<<<dim3(ICH, KSP, BB), 256>>>(u);
        k_sgemm<<<dim3(ISP, BB), 256>>>(u);
        k_caps<<<dim3(NN, BB / CAPS_BL), 256, CAPS_SM>>>(W, pass == 0 ? 1 : 2,
                                                          pass == 0 ? nullptr : out);
    }
}

// round 7
// speedup vs baseline: 1.0014x; 1.0014x over previous
#include <cuda_runtime.h>
#include <cuda_bf16.h>

// Capsule routing, factorized. f32x2 FMA with conflict-free LDS.64 b-operands
// (lane-contiguous pair layout) and LDS.128-broadcast a-operands.
// u (32,1024,256) f32; W (256,2048) f32; out (32,32,64) f32.

#define BB 32
#define II 1024
#define CC 256
#define NN 32
#define DD 64
#define ND 2048

#define KSP 2    // blog k-splits (128 c each)
#define ISP 8    // sgemm i-splits (128 i each)

typedef unsigned long long ull;

__device__ float g_part[BB * 8 * CC];                 // colsum partials
__device__ float g_V[BB * NN * CC];                   // V[b][n][c]
__device__ float g_blogp[KSP * BB * NN * II];         // blog partials
__device__ float g_Spart[ISP * BB * NN * CC];         // S partials

__device__ __forceinline__ ull pack2(float x) {
    ull r; unsigned xi = __float_as_uint(x);
    asm("mov.b64 %0, {%1, %1};" : "=l"(r) : "r"(xi));
    return r;
}
__device__ __forceinline__ void fma2(ull& d, ull a, ull b) {
    asm("fma.rn.f32x2 %0, %1, %2, %0;" : "+l"(d) : "l"(a), "l"(b));
}

// ---- colsum partials ----------------------------------------------------
__global__ void k_colsum_part(const float* __restrict__ u) {
    int q = blockIdx.x, b = blockIdx.y, c = threadIdx.x;
    const float* p = u + (size_t)b * II * CC + (size_t)q * 128 * CC + c;
    float s = 0.f;
#pragma unroll 8
    for (int i = 0; i < 128; i++) s += p[(size_t)i * CC];
    g_part[(b * 8 + q) * CC + c] = s;
}

// ---- blog: blog[b][n][i] = V[b][n][khalf] . u[b][i][khalf] --------------
// grid (ich=4, ks=2, b=32), 256 thr. Tile 32n x 256i, K=128.
// warp: wn=w>>1 (8n group), wi=w&1 (128i half). thread: 8n x 2 i-pairs.
__global__ __launch_bounds__(256) void k_blog(const float* __restrict__ u) {
    __shared__ float sV[NN][132];      // V[n][k 0..127]
    __shared__ float sU[16][260];      // u^T [k16][i 256]
    int ich = blockIdx.x, ks = blockIdx.y, b = blockIdx.z;
    int i0 = ich * 256, kb = ks * 128;
    int t = threadIdx.x, lane = t & 31, w = t >> 5;
    int wn = w >> 1, wi = w & 1;

    // sV: thread t -> n = t>>3, 16 k
    {
        int n = t >> 3, kq = (t & 7) * 16;
        const float* vp = g_V + (size_t)(b * NN + n) * CC + kb + kq;
        float4 v0 = *(const float4*)vp,     v1 = *(const float4*)(vp + 4);
        float4 v2 = *(const float4*)(vp + 8), v3 = *(const float4*)(vp + 12);
        float* d = &sV[n][kq];
        *(float4*)d = v0; *(float4*)(d + 4) = v1;
        *(float4*)(d + 8) = v2; *(float4*)(d + 12) = v3;
    }

    ull acc[8][2] = {};
    int rl = t >> 2, kc = (t & 3) * 4;   // load mapping: 4 lanes per i-row
#pragma unroll
    for (int s = 0; s < 8; s++) {
        float4 ld[4];
#pragma unroll
        for (int r = 0; r < 4; r++)
            ld[r] = *(const float4*)(u + ((size_t)b * II + i0 + rl + 64 * r) * CC
                                       + kb + s * 16 + kc);
        __syncthreads();
#pragma unroll
        for (int r = 0; r < 4; r++) {
            int il = rl + 64 * r;
            sU[kc + 0][il] = ld[r].x; sU[kc + 1][il] = ld[r].y;
            sU[kc + 2][il] = ld[r].z; sU[kc + 3][il] = ld[r].w;
        }
        __syncthreads();
#pragma unroll
        for (int k4 = 0; k4 < 4; k4++) {
            float4 av[8];
#pragma unroll
            for (int j = 0; j < 8; j++)
                av[j] = *(const float4*)&sV[8 * wn + j][s * 16 + k4 * 4];
#pragma unroll
            for (int kk = 0; kk < 4; kk++) {
                const ull* pb = (const ull*)&sU[k4 * 4 + kk][128 * wi];
                ull b0 = pb[lane], b1 = pb[lane + 32];
#pragma unroll
                for (int j = 0; j < 8; j++) {
                    float as = (kk == 0) ? av[j].x : (kk == 1) ? av[j].y
                             : (kk == 2) ? av[j].z : av[j].w;
                    ull a = pack2(as);
                    fma2(acc[j][0], a, b0);
                    fma2(acc[j][1], a, b1);
                }
            }
        }
    }
#pragma unroll
    for (int j = 0; j < 8; j++) {
        ull* op = (ull*)(g_blogp + (((size_t)ks * BB + b) * NN + 8 * wn + j) * II
                                  + i0 + 128 * wi);
        op[lane] = acc[j][0];
        op[lane + 32] = acc[j][1];
    }
}

// ---- sgemm: S[n][c] += softmax_n(blog)[n][iwin] . u[iwin][c] ------------
// grid (isp=8, b=32), 256 thr. Tile 32n x 256c, K=128 i.
__global__ __launch_bounds__(256) void k_sgemm(const float* __restrict__ u) {
    __shared__ float sC[NN][132];      // coeffs [n][i 0..127]
    __shared__ float sU[16][260];      // u [i16][c 256]
    int isp = blockIdx.x, b = blockIdx.y;
    int i1 = isp * 128;
    int t = threadIdx.x, lane = t & 31, w = t >> 5;
    int wn = w >> 1, wc = w & 1;

    // prologue: sum KSP blog partials -> sC
    {
        int n = t >> 3, g = (t & 7) * 16;
        float v[16];
        const float* p0 = g_blogp + ((size_t)(0 * BB + b) * NN + n) * II + i1 + g;
        const float* p1 = g_blogp + ((size_t)(1 * BB + b) * NN + n) * II + i1 + g;
#pragma unroll
        for (int r = 0; r < 4; r++) {
            float4 x = *(const float4*)(p0 + 4 * r);
            float4 y = *(const float4*)(p1 + 4 * r);
            v[4 * r] = x.x + y.x; v[4 * r + 1] = x.y + y.y;
            v[4 * r + 2] = x.z + y.z; v[4 * r + 3] = x.w + y.w;
        }
        float* d = &sC[n][g];
#pragma unroll
        for (int r = 0; r < 4; r++)
            *(float4*)(d + 4 * r) = make_float4(v[4*r], v[4*r+1], v[4*r+2], v[4*r+3]);
    }
    __syncthreads();
    // softmax over n, one i-column per thread
    if (t < 128) {
        float vv[NN];
        float m = -1e30f;
#pragma unroll
        for (int n = 0; n < NN; n++) { vv[n] = sC[n][t]; m = fmaxf(m, vv[n]); }
        float s = 0.f;
#pragma unroll
        for (int n = 0; n < NN; n++) { vv[n] = __expf(vv[n] - m); s += vv[n]; }
        float inv = 1.0f / s;
#pragma unroll
        for (int n = 0; n < NN; n++) sC[n][t] = vv[n] * inv;
    }

    ull acc[8][2] = {};
    int il = t >> 4, c0 = (t & 15) * 16;
#pragma unroll
    for (int s = 0; s < 8; s++) {
        const float* up = u + ((size_t)b * II + i1 + s * 16 + il) * CC + c0;
        float4 a0 = *(const float4*)up,       a1 = *(const float4*)(up + 4);
        float4 a2 = *(const float4*)(up + 8), a3 = *(const float4*)(up + 12);
        __syncthreads();
        float* d = &sU[il][c0];
        *(float4*)d = a0; *(float4*)(d + 4) = a1;
        *(float4*)(d + 8) = a2; *(float4*)(d + 12) = a3;
        __syncthreads();
#pragma unroll
        for (int k4 = 0; k4 < 4; k4++) {
            float4 av[8];
#pragma unroll
            for (int j = 0; j < 8; j++)
                av[j] = *(const float4*)&sC[8 * wn + j][s * 16 + k4 * 4];
#pragma unroll
            for (int kk = 0; kk < 4; kk++) {
                const ull* pb = (const ull*)&sU[k4 * 4 + kk][128 * wc];
                ull b0 = pb[lane], b1 = pb[lane + 32];
#pragma unroll
                for (int j = 0; j < 8; j++) {
                    float as = (kk == 0) ? av[j].x : (kk == 1) ? av[j].y
                             : (kk == 2) ? av[j].z : av[j].w;
                    ull a = pack2(as);
                    fma2(acc[j][0], a, b0);
                    fma2(acc[j][1], a, b1);
                }
            }
        }
    }
#pragma unroll
    for (int j = 0; j < 8; j++) {
        ull* op = (ull*)(g_Spart + (((size_t)isp * BB + b) * NN + 8 * wn + j) * CC
                                  + 128 * wc);
        op[lane] = acc[j][0];
        op[lane + 32] = acc[j][1];
    }
}

// ---- caps: out = squash(S @ W_n), V = out @ W_n^T -----------------------
#define CAPS_BL 8
#define CAPS_SM ((256 * 65 + CAPS_BL * 256 + CAPS_BL * 65) * 4)
__global__ __launch_bounds__(256, 1) void k_caps(const float* __restrict__ W,
                                                 int mode, float* __restrict__ dout) {
    extern __shared__ float sm[];
    float* sW = sm;                      // [256][65]
    float* sS = sm + 256 * 65;           // [8][256]
    float* sO = sS + CAPS_BL * 256;      // [8][65]
    int n = blockIdx.x, bg = blockIdx.y;
    int t = threadIdx.x, lane = t & 31, w = t >> 5;

#pragma unroll
    for (int r = 0; r < 32; r++) {
        int c = w + 8 * r;
        const float* wp = W + (size_t)c * ND + n * DD;
        sW[c * 65 + lane] = wp[lane];
        sW[c * 65 + lane + 32] = wp[lane + 32];
    }
#pragma unroll
    for (int bl = 0; bl < CAPS_BL; bl++) {
        int b = bg * CAPS_BL + bl;
        float s = 0.f;
        if (mode == 0) {
#pragma unroll
            for (int q = 0; q < 8; q++) s += g_part[(b * 8 + q) * CC + t];
            s *= (1.0f / 32.0f);
        } else {
#pragma unroll
            for (int q = 0; q < ISP; q++)
                s += g_Spart[(((size_t)q * BB + b) * NN + n) * CC + t];
        }
        sS[bl * CC + t] = s;
    }
    __syncthreads();

    float a0 = 0.f, a1 = 0.f;
    for (int k = 0; k < CC; k++) {
        float s = sS[w * CC + k];
        a0 += s * sW[k * 65 + lane];
        a1 += s * sW[k * 65 + lane + 32];
    }
    float sq = a0 * a0 + a1 * a1;
#pragma unroll
    for (int off = 16; off; off >>= 1) sq += __shfl_xor_sync(0xffffffffu, sq, off);
    float f = rsqrtf(sq + 1e-7f);
    a0 *= f; a1 *= f;
    sO[w * 65 + lane] = a0; sO[w * 65 + lane + 32] = a1;
    if (mode == 2) {
        int b = bg * CAPS_BL + w;
        dout[(size_t)(b * NN + n) * DD + lane] = a0;
        dout[(size_t)(b * NN + n) * DD + lane + 32] = a1;
        return;
    }
    __syncthreads();

    float accB[8] = {};
    for (int k = 0; k < DD; k++) {
        float a = sO[w * 65 + k];
#pragma unroll
        for (int q = 0; q < 8; q++) accB[q] += a * sW[(lane + 32 * q) * 65 + k];
    }
    int b = bg * CAPS_BL + w;
#pragma unroll
    for (int q = 0; q < 8; q++)
        g_V[(size_t)(b * NN + n) * CC + lane + 32 * q] = accB[q];
}

// ---------------------------------------------------------------------------
extern "C" void kernel_launch(void* const* d_in, const int* in_sizes, int n_in,
                              void* d_out, int out_size) {
    const float* u = (const float*)d_in[0];
    const float* W = (const float*)d_in[1];
    if (n_in >= 2 && in_sizes[0] == CC * ND) {
        u = (const float*)d_in[1];
        W = (const float*)d_in[0];
    }
    float* out = (float*)d_out;

    cudaFuncSetAttribute(k_caps, cudaFuncAttributeMaxDynamicSharedMemorySize, CAPS_SM);

    k_colsum_part<<<dim3(8, BB), 256>>>(u);
    k_caps<<<dim3(NN, BB / CAPS_BL), 256, CAPS_SM>>>(W, 0, nullptr);

    for (int pass = 0; pass < 2; pass++) {
        k_blog<<<dim3(4, KSP, BB), 256>>>(u);
        k_sgemm<<<dim3(ISP, BB), 256>>>(u);
        k_caps<<<dim3(NN, BB / CAPS_BL), 256, CAPS_SM>>>(W, pass == 0 ? 1 : 2,
                                                          pass == 0 ? nullptr : out);
    }
}

// round 8
// speedup vs baseline: 1.4013x; 1.3992x over previous
#include <cuda_runtime.h>
#include <cuda_bf16.h>

// Capsule routing, factorized. f32x2 FMA, conflict-free LDS, software-pipelined
// double-buffered GEMM kernels at 512 blocks / 128 threads.
// u (32,1024,256) f32; W (256,2048) f32; out (32,32,64) f32.

#define BB 32
#define II 1024
#define CC 256
#define NN 32
#define DD 64
#define ND 2048

#define KSP 2    // blog c-splits
#define ISP 8    // sgemm i-splits

typedef unsigned long long ull;

__device__ float g_part[BB * 8 * CC];
__device__ float g_V[BB * NN * CC];
__device__ float g_blogp[KSP * BB * NN * II];
__device__ float g_Spart[ISP * BB * NN * CC];

__device__ __forceinline__ ull pack2(float x) {
    ull r; unsigned xi = __float_as_uint(x);
    asm("mov.b64 %0, {%1, %1};" : "=l"(r) : "r"(xi));
    return r;
}
__device__ __forceinline__ void fma2(ull& d, ull a, ull b) {
    asm("fma.rn.f32x2 %0, %1, %2, %0;" : "+l"(d) : "l"(a), "l"(b));
}

// ---- colsum partials ----------------------------------------------------
__global__ void k_colsum_part(const float* __restrict__ u) {
    int q = blockIdx.x, b = blockIdx.y, c = threadIdx.x;
    const float* p = u + (size_t)b * II * CC + (size_t)q * 128 * CC + c;
    float s = 0.f;
#pragma unroll 8
    for (int i = 0; i < 128; i++) s += p[(size_t)i * CC];
    g_part[(b * 8 + q) * CC + c] = s;
}

// ---- blog: blog[b][n][i] = V[b][n][kh] . u[b][i][kh] --------------------
// grid (ich=8, ks=2, b=32) = 512 blocks, 128 thr. Tile 32n x 128i, K=128.
// warp w -> n-octet; lane -> i-pairs {2l, 2l+1} and {64+2l, 65+2l}.
__global__ __launch_bounds__(128) void k_blog(const float* __restrict__ u) {
    __shared__ float sV[NN][132];
    __shared__ float sU[2][16][132];
    int ich = blockIdx.x, ks = blockIdx.y, b = blockIdx.z;
    int i0 = ich * 128, kb = ks * 128;
    int t = threadIdx.x, lane = t & 31, w = t >> 5;

    {   // V slice [32n][128k]
        int n = t >> 2, kq = (t & 3) * 32;
        const float* vp = g_V + (size_t)(b * NN + n) * CC + kb + kq;
        float* d = &sV[n][kq];
#pragma unroll
        for (int r = 0; r < 8; r++) *(float4*)(d + 4 * r) = *(const float4*)(vp + 4 * r);
    }

    const float* ubase = u + ((size_t)b * II + i0 + t) * CC + kb;  // row t
    float4 l0, l1, l2, l3;
#define BLOAD(s) { const float4* p = (const float4*)(ubase + (s) * 16); \
    l0 = p[0]; l1 = p[1]; l2 = p[2]; l3 = p[3]; }
#define BSTS(bf) { \
    sU[bf][0][t]=l0.x;  sU[bf][1][t]=l0.y;  sU[bf][2][t]=l0.z;  sU[bf][3][t]=l0.w;  \
    sU[bf][4][t]=l1.x;  sU[bf][5][t]=l1.y;  sU[bf][6][t]=l1.z;  sU[bf][7][t]=l1.w;  \
    sU[bf][8][t]=l2.x;  sU[bf][9][t]=l2.y;  sU[bf][10][t]=l2.z; sU[bf][11][t]=l2.w; \
    sU[bf][12][t]=l3.x; sU[bf][13][t]=l3.y; sU[bf][14][t]=l3.z; sU[bf][15][t]=l3.w; }

    BLOAD(0); BSTS(0); BLOAD(1);
    __syncthreads();                      // sV + buf0 ready

    ull acc[8][2] = {};
#pragma unroll
    for (int s = 0; s < 8; s++) {
        if (s < 7) { BSTS((s + 1) & 1); }
        if (s < 6) BLOAD(s + 2);
#pragma unroll
        for (int k4 = 0; k4 < 4; k4++) {
            float4 av[8];
#pragma unroll
            for (int j = 0; j < 8; j++)
                av[j] = *(const float4*)&sV[8 * w + j][s * 16 + 4 * k4];
#pragma unroll
            for (int kk = 0; kk < 4; kk++) {
                const ull* pb = (const ull*)&sU[s & 1][4 * k4 + kk][0];
                ull b0 = pb[lane], b1 = pb[lane + 32];
#pragma unroll
                for (int j = 0; j < 8; j++) {
                    float as = (kk == 0) ? av[j].x : (kk == 1) ? av[j].y
                             : (kk == 2) ? av[j].z : av[j].w;
                    ull a = pack2(as);
                    fma2(acc[j][0], a, b0);
                    fma2(acc[j][1], a, b1);
                }
            }
        }
        __syncthreads();
    }
#pragma unroll
    for (int j = 0; j < 8; j++) {
        ull* op = (ull*)(g_blogp + (((size_t)ks * BB + b) * NN + 8 * w + j) * II + i0);
        op[lane] = acc[j][0];
        op[lane + 32] = acc[j][1];
    }
}

// ---- sgemm: S[n][cg] += softmax_n(blog)[n][iwin] . u[iwin][cg] ----------
// grid (isp=8, ch=2, b=32) = 512 blocks, 128 thr. Tile 32n x 128c, K=128 i.
__global__ __launch_bounds__(128) void k_sgemm(const float* __restrict__ u) {
    __shared__ float sC[NN][132];
    __shared__ float sU[2][16][132];
    int isp = blockIdx.x, ch = blockIdx.y, b = blockIdx.z;
    int i1 = isp * 128, cg = ch * 128;
    int t = threadIdx.x, lane = t & 31, w = t >> 5;

    const float* ubase = u + ((size_t)b * II + i1 + (t >> 3)) * CC + cg + (t & 7) * 16;
    float4 l0, l1, l2, l3;
#define SLOAD(s) { const float4* p = (const float4*)(ubase + (size_t)(s) * 16 * CC); \
    l0 = p[0]; l1 = p[1]; l2 = p[2]; l3 = p[3]; }
#define SSTS(bf) { float* d = &sU[bf][t >> 3][(t & 7) * 16]; \
    *(float4*)d = l0; *(float4*)(d + 4) = l1; \
    *(float4*)(d + 8) = l2; *(float4*)(d + 12) = l3; }

    SLOAD(0);
    {   // sum KSP blog partials -> sC (raw logits)
        int n = t >> 2, g = (t & 3) * 32;
        const float* p0 = g_blogp + ((size_t)b * NN + n) * II + i1 + g;
        const float* p1 = g_blogp + (((size_t)BB + b) * NN + n) * II + i1 + g;
        float* d = &sC[n][g];
#pragma unroll
        for (int r = 0; r < 8; r++) {
            float4 x = ((const float4*)p0)[r], y = ((const float4*)p1)[r];
            *(float4*)(d + 4 * r) =
                make_float4(x.x + y.x, x.y + y.y, x.z + y.z, x.w + y.w);
        }
    }
    __syncthreads();
    {   // softmax over n, column i = t
        float vv[NN];
        float m = -1e30f;
#pragma unroll
        for (int n = 0; n < NN; n++) { vv[n] = sC[n][t]; m = fmaxf(m, vv[n]); }
        float s = 0.f;
#pragma unroll
        for (int n = 0; n < NN; n++) { vv[n] = __expf(vv[n] - m); s += vv[n]; }
        float inv = 1.0f / s;
#pragma unroll
        for (int n = 0; n < NN; n++) sC[n][t] = vv[n] * inv;
    }
    SSTS(0); SLOAD(1);
    __syncthreads();                      // sC + buf0 ready

    ull acc[8][2] = {};
#pragma unroll
    for (int s = 0; s < 8; s++) {
        if (s < 7) { SSTS((s + 1) & 1); }
        if (s < 6) SLOAD(s + 2);
#pragma unroll
        for (int k4 = 0; k4 < 4; k4++) {
            float4 av[8];
#pragma unroll
            for (int j = 0; j < 8; j++)
                av[j] = *(const float4*)&sC[8 * w + j][s * 16 + 4 * k4];
#pragma unroll
            for (int kk = 0; kk < 4; kk++) {
                const ull* pb = (const ull*)&sU[s & 1][4 * k4 + kk][0];
                ull b0 = pb[lane], b1 = pb[lane + 32];
#pragma unroll
                for (int j = 0; j < 8; j++) {
                    float as = (kk == 0) ? av[j].x : (kk == 1) ? av[j].y
                             : (kk == 2) ? av[j].z : av[j].w;
                    ull a = pack2(as);
                    fma2(acc[j][0], a, b0);
                    fma2(acc[j][1], a, b1);
                }
            }
        }
        __syncthreads();
    }
#pragma unroll
    for (int j = 0; j < 8; j++) {
        ull* op = (ull*)(g_Spart + (((size_t)isp * BB + b) * NN + 8 * w + j) * CC + cg);
        op[lane] = acc[j][0];
        op[lane + 32] = acc[j][1];
    }
}

// ---- caps: out = squash(S @ W_n), V = out @ W_n^T -----------------------
#define CAPS_BL 8
#define CAPS_SM ((256 * 65 + CAPS_BL * 256 + CAPS_BL * 65) * 4)
__global__ __launch_bounds__(256, 1) void k_caps(const float* __restrict__ W,
                                                 int mode, float* __restrict__ dout) {
    extern __shared__ float sm[];
    float* sW = sm;                      // [256][65]
    float* sS = sm + 256 * 65;           // [8][256]
    float* sO = sS + CAPS_BL * 256;      // [8][65]
    int n = blockIdx.x, bg = blockIdx.y;
    int t = threadIdx.x, lane = t & 31, w = t >> 5;

#pragma unroll
    for (int r = 0; r < 32; r++) {
        int c = w + 8 * r;
        const float* wp = W + (size_t)c * ND + n * DD;
        sW[c * 65 + lane] = wp[lane];
        sW[c * 65 + lane + 32] = wp[lane + 32];
    }
#pragma unroll
    for (int bl = 0; bl < CAPS_BL; bl++) {
        int b = bg * CAPS_BL + bl;
        float s = 0.f;
        if (mode == 0) {
#pragma unroll
            for (int q = 0; q < 8; q++) s += g_part[(b * 8 + q) * CC + t];
            s *= (1.0f / 32.0f);
        } else {
#pragma unroll
            for (int q = 0; q < ISP; q++)
                s += g_Spart[(((size_t)q * BB + b) * NN + n) * CC + t];
        }
        sS[bl * CC + t] = s;
    }
    __syncthreads();

    float a0 = 0.f, a1 = 0.f;
    for (int k = 0; k < CC; k++) {
        float s = sS[w * CC + k];
        a0 += s * sW[k * 65 + lane];
        a1 += s * sW[k * 65 + lane + 32];
    }
    float sq = a0 * a0 + a1 * a1;
#pragma unroll
    for (int off = 16; off; off >>= 1) sq += __shfl_xor_sync(0xffffffffu, sq, off);
    float f = rsqrtf(sq + 1e-7f);
    a0 *= f; a1 *= f;
    sO[w * 65 + lane] = a0; sO[w * 65 + lane + 32] = a1;
    if (mode == 2) {
        int b = bg * CAPS_BL + w;
        dout[(size_t)(b * NN + n) * DD + lane] = a0;
        dout[(size_t)(b * NN + n) * DD + lane + 32] = a1;
        return;
    }
    __syncthreads();

    float accB[8] = {};
    for (int k = 0; k < DD; k++) {
        float a = sO[w * 65 + k];
#pragma unroll
        for (int q = 0; q < 8; q++) accB[q] += a * sW[(lane + 32 * q) * 65 + k];
    }
    int b = bg * CAPS_BL + w;
#pragma unroll
    for (int q = 0; q < 8; q++)
        g_V[(size_t)(b * NN + n) * CC + lane + 32 * q] = accB[q];
}

// ---------------------------------------------------------------------------
extern "C" void kernel_launch(void* const* d_in, const int* in_sizes, int n_in,
                              void* d_out, int out_size) {
    const float* u = (const float*)d_in[0];
    const float* W = (const float*)d_in[1];
    if (n_in >= 2 && in_sizes[0] == CC * ND) {
        u = (const float*)d_in[1];
        W = (const float*)d_in[0];
    }
    float* out = (float*)d_out;

    cudaFuncSetAttribute(k_caps, cudaFuncAttributeMaxDynamicSharedMemorySize, CAPS_SM);

    k_colsum_part<<<dim3(8, BB), 256>>>(u);
    k_caps<<<dim3(NN, BB / CAPS_BL), 256, CAPS_SM>>>(W, 0, nullptr);

    for (int pass = 0; pass < 2; pass++) {
        k_blog<<<dim3(8, KSP, BB), 128>>>(u);
        k_sgemm<<<dim3(ISP, 2, BB), 128>>>(u);
        k_caps<<<dim3(NN, BB / CAPS_BL), 256, CAPS_SM>>>(W, pass == 0 ? 1 : 2,
                                                          pass == 0 ? nullptr : out);
    }
}

// round 9
// speedup vs baseline: 1.4552x; 1.0385x over previous
#include <cuda_runtime.h>
#include <cuda_bf16.h>

// Capsule routing, factorized. f32x2 FMA, conflict-free LDS, double-buffered
// pipeline, 1024-block grids for occupancy.
// u (32,1024,256) f32; W (256,2048) f32; out (32,32,64) f32.

#define BB 32
#define II 1024
#define CC 256
#define NN 32
#define DD 64
#define ND 2048

#define KSP 4    // blog c-splits (64 c each)
#define ISP 16   // sgemm i-splits (64 i each)

typedef unsigned long long ull;

__device__ float g_part[BB * 8 * CC];
__device__ float g_V[BB * NN * CC];
__device__ float g_blogp[KSP * BB * NN * II];
__device__ float g_Spart[ISP * BB * NN * CC];

__device__ __forceinline__ ull pack2(float x) {
    ull r; unsigned xi = __float_as_uint(x);
    asm("mov.b64 %0, {%1, %1};" : "=l"(r) : "r"(xi));
    return r;
}
__device__ __forceinline__ void fma2(ull& d, ull a, ull b) {
    asm("fma.rn.f32x2 %0, %1, %2, %0;" : "+l"(d) : "l"(a), "l"(b));
}

// ---- colsum partials ----------------------------------------------------
__global__ void k_colsum_part(const float* __restrict__ u) {
    int q = blockIdx.x, b = blockIdx.y, c = threadIdx.x;
    const float* p = u + (size_t)b * II * CC + (size_t)q * 128 * CC + c;
    float s = 0.f;
#pragma unroll 8
    for (int i = 0; i < 128; i++) s += p[(size_t)i * CC];
    g_part[(b * 8 + q) * CC + c] = s;
}

// ---- blog: blog[b][n][i] = V[b][n][kq] . u[b][i][kq] --------------------
// grid (ich=8, ks=4, b=32) = 1024 blocks, 128 thr. Tile 32n x 128i, K=64.
__global__ __launch_bounds__(128) void k_blog(const float* __restrict__ u) {
    __shared__ float sV[NN][68];       // V[n][k 0..63]
    __shared__ float sU[2][16][132];   // u^T [k16][i 128]
    int ich = blockIdx.x, ks = blockIdx.y, b = blockIdx.z;
    int i0 = ich * 128, kb = ks * 64;
    int t = threadIdx.x, lane = t & 31, w = t >> 5;

    {   // V slice [32n][64k]
        int n = t >> 2, kq = (t & 3) * 16;
        const float* vp = g_V + (size_t)(b * NN + n) * CC + kb + kq;
        float* d = &sV[n][kq];
#pragma unroll
        for (int r = 0; r < 4; r++) *(float4*)(d + 4 * r) = *(const float4*)(vp + 4 * r);
    }

    const float* ubase = u + ((size_t)b * II + i0 + t) * CC + kb;  // row t
    float4 l0, l1, l2, l3;
#define BLOAD(s) { const float4* p = (const float4*)(ubase + (s) * 16); \
    l0 = p[0]; l1 = p[1]; l2 = p[2]; l3 = p[3]; }
#define BSTS(bf) { \
    sU[bf][0][t]=l0.x;  sU[bf][1][t]=l0.y;  sU[bf][2][t]=l0.z;  sU[bf][3][t]=l0.w;  \
    sU[bf][4][t]=l1.x;  sU[bf][5][t]=l1.y;  sU[bf][6][t]=l1.z;  sU[bf][7][t]=l1.w;  \
    sU[bf][8][t]=l2.x;  sU[bf][9][t]=l2.y;  sU[bf][10][t]=l2.z; sU[bf][11][t]=l2.w; \
    sU[bf][12][t]=l3.x; sU[bf][13][t]=l3.y; sU[bf][14][t]=l3.z; sU[bf][15][t]=l3.w; }

    BLOAD(0); BSTS(0); BLOAD(1);
    __syncthreads();

    ull acc[8][2] = {};
#pragma unroll
    for (int s = 0; s < 4; s++) {
        if (s < 3) { BSTS((s + 1) & 1); }
        if (s < 2) BLOAD(s + 2);
#pragma unroll
        for (int k4 = 0; k4 < 4; k4++) {
            float4 av[8];
#pragma unroll
            for (int j = 0; j < 8; j++)
                av[j] = *(const float4*)&sV[8 * w + j][s * 16 + 4 * k4];
#pragma unroll
            for (int kk = 0; kk < 4; kk++) {
                const ull* pb = (const ull*)&sU[s & 1][4 * k4 + kk][0];
                ull b0 = pb[lane], b1 = pb[lane + 32];
#pragma unroll
                for (int j = 0; j < 8; j++) {
                    float as = (kk == 0) ? av[j].x : (kk == 1) ? av[j].y
                             : (kk == 2) ? av[j].z : av[j].w;
                    ull a = pack2(as);
                    fma2(acc[j][0], a, b0);
                    fma2(acc[j][1], a, b1);
                }
            }
        }
        __syncthreads();
    }
#pragma unroll
    for (int j = 0; j < 8; j++) {
        ull* op = (ull*)(g_blogp + (((size_t)ks * BB + b) * NN + 8 * w + j) * II + i0);
        op[lane] = acc[j][0];
        op[lane + 32] = acc[j][1];
    }
}

// ---- sgemm: S[n][cg] += softmax_n(blog)[n][iwin] . u[iwin][cg] ----------
// grid (isp=16, ch=2, b=32) = 1024 blocks, 128 thr. Tile 32n x 128c, K=64 i.
__global__ __launch_bounds__(128) void k_sgemm(const float* __restrict__ u) {
    __shared__ float sC[NN][68];       // coeffs [n][i 0..63]
    __shared__ float sU[2][16][132];   // u [i16][c 128]
    int isp = blockIdx.x, ch = blockIdx.y, b = blockIdx.z;
    int i1 = isp * 64, cg = ch * 128;
    int t = threadIdx.x, lane = t & 31, w = t >> 5;

    const float* ubase = u + ((size_t)b * II + i1 + (t >> 3)) * CC + cg + (t & 7) * 16;
    float4 l0, l1, l2, l3;
#define SLOAD(s) { const float4* p = (const float4*)(ubase + (size_t)(s) * 16 * CC); \
    l0 = p[0]; l1 = p[1]; l2 = p[2]; l3 = p[3]; }
#define SSTS(bf) { float* d = &sU[bf][t >> 3][(t & 7) * 16]; \
    *(float4*)d = l0; *(float4*)(d + 4) = l1; \
    *(float4*)(d + 8) = l2; *(float4*)(d + 12) = l3; }

    SLOAD(0);
    {   // sum KSP blog partials -> sC (raw logits)
        int n = t >> 2, g = (t & 3) * 16;
        float v[16] = {};
#pragma unroll
        for (int ks = 0; ks < KSP; ks++) {
            const float* p = g_blogp + (((size_t)ks * BB + b) * NN + n) * II + i1 + g;
#pragma unroll
            for (int r = 0; r < 4; r++) {
                float4 x = ((const float4*)p)[r];
                v[4*r] += x.x; v[4*r+1] += x.y; v[4*r+2] += x.z; v[4*r+3] += x.w;
            }
        }
        float* d = &sC[n][g];
#pragma unroll
        for (int r = 0; r < 4; r++)
            *(float4*)(d + 4 * r) = make_float4(v[4*r], v[4*r+1], v[4*r+2], v[4*r+3]);
    }
    __syncthreads();
    if (t < 64) {   // softmax over n, column i = t
        float vv[NN];
        float m = -1e30f;
#pragma unroll
        for (int n = 0; n < NN; n++) { vv[n] = sC[n][t]; m = fmaxf(m, vv[n]); }
        float s = 0.f;
#pragma unroll
        for (int n = 0; n < NN; n++) { vv[n] = __expf(vv[n] - m); s += vv[n]; }
        float inv = 1.0f / s;
#pragma unroll
        for (int n = 0; n < NN; n++) sC[n][t] = vv[n] * inv;
    }
    SSTS(0); SLOAD(1);
    __syncthreads();

    ull acc[8][2] = {};
#pragma unroll
    for (int s = 0; s < 4; s++) {
        if (s < 3) { SSTS((s + 1) & 1); }
        if (s < 2) SLOAD(s + 2);
#pragma unroll
        for (int k4 = 0; k4 < 4; k4++) {
            float4 av[8];
#pragma unroll
            for (int j = 0; j < 8; j++)
                av[j] = *(const float4*)&sC[8 * w + j][s * 16 + 4 * k4];
#pragma unroll
            for (int kk = 0; kk < 4; kk++) {
                const ull* pb = (const ull*)&sU[s & 1][4 * k4 + kk][0];
                ull b0 = pb[lane], b1 = pb[lane + 32];
#pragma unroll
                for (int j = 0; j < 8; j++) {
                    float as = (kk == 0) ? av[j].x : (kk == 1) ? av[j].y
                             : (kk == 2) ? av[j].z : av[j].w;
                    ull a = pack2(as);
                    fma2(acc[j][0], a, b0);
                    fma2(acc[j][1], a, b1);
                }
            }
        }
        __syncthreads();
    }
#pragma unroll
    for (int j = 0; j < 8; j++) {
        ull* op = (ull*)(g_Spart + (((size_t)isp * BB + b) * NN + 8 * w + j) * CC + cg);
        op[lane] = acc[j][0];
        op[lane + 32] = acc[j][1];
    }
}

// ---- caps: out = squash(S @ W_n), V = out @ W_n^T -----------------------
#define CAPS_BL 8
#define CAPS_SM ((256 * 65 + CAPS_BL * 256 + CAPS_BL * 65) * 4)
__global__ __launch_bounds__(256, 1) void k_caps(const float* __restrict__ W,
                                                 int mode, float* __restrict__ dout) {
    extern __shared__ float sm[];
    float* sW = sm;                      // [256][65]
    float* sS = sm + 256 * 65;           // [8][256]
    float* sO = sS + CAPS_BL * 256;      // [8][65]
    int n = blockIdx.x, bg = blockIdx.y;
    int t = threadIdx.x, lane = t & 31, w = t >> 5;

#pragma unroll
    for (int r = 0; r < 32; r++) {
        int c = w + 8 * r;
        const float* wp = W + (size_t)c * ND + n * DD;
        sW[c * 65 + lane] = wp[lane];
        sW[c * 65 + lane + 32] = wp[lane + 32];
    }
#pragma unroll
    for (int bl = 0; bl < CAPS_BL; bl++) {
        int b = bg * CAPS_BL + bl;
        float s = 0.f;
        if (mode == 0) {
#pragma unroll
            for (int q = 0; q < 8; q++) s += g_part[(b * 8 + q) * CC + t];
            s *= (1.0f / 32.0f);
        } else {
#pragma unroll
            for (int q = 0; q < ISP; q++)
                s += g_Spart[(((size_t)q * BB + b) * NN + n) * CC + t];
        }
        sS[bl * CC + t] = s;
    }
    __syncthreads();

    float a0 = 0.f, a1 = 0.f;
    for (int k = 0; k < CC; k++) {
        float s = sS[w * CC + k];
        a0 += s * sW[k * 65 + lane];
        a1 += s * sW[k * 65 + lane + 32];
    }
    float sq = a0 * a0 + a1 * a1;
#pragma unroll
    for (int off = 16; off; off >>= 1) sq += __shfl_xor_sync(0xffffffffu, sq, off);
    float f = rsqrtf(sq + 1e-7f);
    a0 *= f; a1 *= f;
    sO[w * 65 + lane] = a0; sO[w * 65 + lane + 32] = a1;
    if (mode == 2) {
        int b = bg * CAPS_BL + w;
        dout[(size_t)(b * NN + n) * DD + lane] = a0;
        dout[(size_t)(b * NN + n) * DD + lane + 32] = a1;
        return;
    }
    __syncthreads();

    float accB[8] = {};
    for (int k = 0; k < DD; k++) {
        float a = sO[w * 65 + k];
#pragma unroll
        for (int q = 0; q < 8; q++) accB[q] += a * sW[(lane + 32 * q) * 65 + k];
    }
    int b = bg * CAPS_BL + w;
#pragma unroll
    for (int q = 0; q < 8; q++)
        g_V[(size_t)(b * NN + n) * CC + lane + 32 * q] = accB[q];
}

// ---------------------------------------------------------------------------
extern "C" void kernel_launch(void* const* d_in, const int* in_sizes, int n_in,
                              void* d_out, int out_size) {
    const float* u = (const float*)d_in[0];
    const float* W = (const float*)d_in[1];
    if (n_in >= 2 && in_sizes[0] == CC * ND) {
        u = (const float*)d_in[1];
        W = (const float*)d_in[0];
    }
    float* out = (float*)d_out;

    cudaFuncSetAttribute(k_caps, cudaFuncAttributeMaxDynamicSharedMemorySize, CAPS_SM);

    k_colsum_part<<<dim3(8, BB), 256>>>(u);
    k_caps<<<dim3(NN, BB / CAPS_BL), 256, CAPS_SM>>>(W, 0, nullptr);

    for (int pass = 0; pass < 2; pass++) {
        k_blog<<<dim3(8, KSP, BB), 128>>>(u);
        k_sgemm<<<dim3(ISP, 2, BB), 128>>>(u);
        k_caps<<<dim3(NN, BB / CAPS_BL), 256, CAPS_SM>>>(W, pass == 0 ? 1 : 2,
                                                          pass == 0 ? nullptr : out);
    }
}

// round 10
// speedup vs baseline: 2.4266x; 1.6675x over previous
#include <cuda_runtime.h>
#include <cuda_bf16.h>
#include <cstdint>

// Capsule routing, factorized. Routing GEMMs on tensor cores (tf32 mma.sync),
// softmax fused into blog kernel; caps/colsum stay fp32 scalar.
// u (32,1024,256) f32; W (256,2048) f32; out (32,32,64) f32.

#define BB 32
#define II 1024
#define CC 256
#define NN 32
#define DD 64
#define ND 2048
#define ISP 8    // sgemm i-splits

typedef unsigned int uint;

__device__ float g_part[BB * 8 * CC];          // colsum partials
__device__ float g_V[BB * NN * CC];            // V[b][n][c]
__device__ float g_coef[BB * II * NN];         // softmaxed coefs [b][i][n]
__device__ float g_Spart[ISP * BB * NN * CC];  // S partials [isp][b][n][c]

__device__ __forceinline__ uint tf32c(float f) {
    uint r; asm("cvt.rna.tf32.f32 %0, %1;" : "=r"(r) : "f"(f)); return r;
}
__device__ __forceinline__ void mma_tf32(float* d, uint a0, uint a1, uint a2, uint a3,
                                         uint b0, uint b1) {
    asm("mma.sync.aligned.m16n8k8.row.col.f32.tf32.tf32.f32 "
        "{%0,%1,%2,%3},{%4,%5,%6,%7},{%8,%9},{%0,%1,%2,%3};"
        : "+f"(d[0]), "+f"(d[1]), "+f"(d[2]), "+f"(d[3])
        : "r"(a0), "r"(a1), "r"(a2), "r"(a3), "r"(b0), "r"(b1));
}
__device__ __forceinline__ uint4 cvt4(float4 v) {
    return make_uint4(tf32c(v.x), tf32c(v.y), tf32c(v.z), tf32c(v.w));
}

// ---- colsum partials ----------------------------------------------------
__global__ void k_colsum_part(const float* __restrict__ u) {
    int q = blockIdx.x, b = blockIdx.y, c = threadIdx.x;
    const float* p = u + (size_t)b * II * CC + (size_t)q * 128 * CC + c;
    float s = 0.f;
#pragma unroll 8
    for (int i = 0; i < 128; i++) s += p[(size_t)i * CC];
    g_part[(b * 8 + q) * CC + c] = s;
}

// ---- blog + softmax: coef[b][i][n] = softmax_n( u[b][i][:] . V[b][n][:] )
// grid (ich=16, b=32), 128 thr. CTA tile 64i x 32n, K=256 in 8 chunks of 32.
// warp w -> i rows [w*16, w*16+16) (one m16 tile); 4 n8 tiles.
__global__ __launch_bounds__(128) void k_blog(const float* __restrict__ u) {
    __shared__ uint sU[2][64][36];   // tf32 u chunk [i][k]
    __shared__ uint sV[2][32][36];   // tf32 V chunk [n][k]
    int ich = blockIdx.x, b = blockIdx.y;
    int i0 = ich * 64;
    int t = threadIdx.x, lane = t & 31, w = t >> 5;
    int g4 = lane >> 2, j4 = lane & 3;

    float4 uf[4], vf[2];
#define BLOADCH(kb) { \
    _Pragma("unroll") for (int it = 0; it < 4; it++) { int idx = it * 128 + t; \
        uf[it] = *(const float4*)(u + ((size_t)b * II + i0 + (idx >> 3)) * CC + (kb) + (idx & 7) * 4); } \
    _Pragma("unroll") for (int it = 0; it < 2; it++) { int idx = it * 128 + t; \
        vf[it] = *(const float4*)(g_V + ((size_t)b * NN + (idx >> 3)) * CC + (kb) + (idx & 7) * 4); } }
#define BSTSCH(bf) { \
    _Pragma("unroll") for (int it = 0; it < 4; it++) { int idx = it * 128 + t; \
        *(uint4*)&sU[bf][idx >> 3][(idx & 7) * 4] = cvt4(uf[it]); } \
    _Pragma("unroll") for (int it = 0; it < 2; it++) { int idx = it * 128 + t; \
        *(uint4*)&sV[bf][idx >> 3][(idx & 7) * 4] = cvt4(vf[it]); } }

    BLOADCH(0); BSTSCH(0); BLOADCH(32);
    __syncthreads();

    float acc[4][4] = {};
#pragma unroll
    for (int s = 0; s < 8; s++) {
        if (s < 7) { BSTSCH((s + 1) & 1); }
        if (s < 6) BLOADCH((s + 2) * 32);
        int bf = s & 1;
#pragma unroll
        for (int ks = 0; ks < 4; ks++) {
            int k0 = ks * 8;
            uint a0 = sU[bf][w * 16 + g4][k0 + j4];
            uint a1 = sU[bf][w * 16 + g4 + 8][k0 + j4];
            uint a2 = sU[bf][w * 16 + g4][k0 + j4 + 4];
            uint a3 = sU[bf][w * 16 + g4 + 8][k0 + j4 + 4];
#pragma unroll
            for (int nt = 0; nt < 4; nt++) {
                uint b0 = sV[bf][nt * 8 + g4][k0 + j4];
                uint b1 = sV[bf][nt * 8 + g4][k0 + j4 + 4];
                mma_tf32(acc[nt], a0, a1, a2, a3, b0, b1);
            }
        }
        __syncthreads();
    }

    // softmax over n: row r0 = i0+w*16+g4 -> {acc[nt][0..1]}, row r1 = r0+8 -> {acc[nt][2..3]}
#pragma unroll
    for (int h = 0; h < 2; h++) {
        float m = -1e30f;
#pragma unroll
        for (int nt = 0; nt < 4; nt++)
            m = fmaxf(m, fmaxf(acc[nt][2 * h], acc[nt][2 * h + 1]));
        m = fmaxf(m, __shfl_xor_sync(0xffffffffu, m, 1));
        m = fmaxf(m, __shfl_xor_sync(0xffffffffu, m, 2));
        float s = 0.f;
#pragma unroll
        for (int nt = 0; nt < 4; nt++) {
            acc[nt][2 * h] = __expf(acc[nt][2 * h] - m);
            acc[nt][2 * h + 1] = __expf(acc[nt][2 * h + 1] - m);
            s += acc[nt][2 * h] + acc[nt][2 * h + 1];
        }
        s += __shfl_xor_sync(0xffffffffu, s, 1);
        s += __shfl_xor_sync(0xffffffffu, s, 2);
        float inv = 1.0f / s;
        int row = i0 + w * 16 + g4 + 8 * h;
        float* cp = g_coef + ((size_t)b * II + row) * NN + 2 * j4;
#pragma unroll
        for (int nt = 0; nt < 4; nt++)
            *(float2*)(cp + nt * 8) =
                make_float2(acc[nt][2 * h] * inv, acc[nt][2 * h + 1] * inv);
    }
}

// ---- sgemm: Spart[n][c] = sum_{i in window} coef[i][n] * u[i][c] --------
// grid (isp=8, ch=2, b=32), 128 thr. CTA tile 32n x 128c, K=128 i, 4 chunks.
// warp w -> c slice [w*32, w*32+32); 2 m16 n-tiles x 4 n8 c-tiles.
__global__ __launch_bounds__(128) void k_sgemm(const float* __restrict__ u) {
    __shared__ uint sU[2][32][132];  // tf32 u chunk [i][c 128]
    __shared__ uint sC[2][32][36];   // tf32 coef chunk [i][n]
    int isp = blockIdx.x, ch = blockIdx.y, b = blockIdx.z;
    int i1 = isp * 128, c0g = ch * 128;
    int t = threadIdx.x, lane = t & 31, w = t >> 5;
    int g4 = lane >> 2, j4 = lane & 3;

    float4 uf[8], cf[2];
#define SLOADCH(kb) { \
    _Pragma("unroll") for (int it = 0; it < 8; it++) { int idx = it * 128 + t; \
        uf[it] = *(const float4*)(u + ((size_t)b * II + i1 + (kb) + (idx >> 5)) * CC + c0g + (idx & 31) * 4); } \
    _Pragma("unroll") for (int it = 0; it < 2; it++) { int idx = it * 128 + t; \
        cf[it] = *(const float4*)(g_coef + ((size_t)b * II + i1 + (kb) + (idx >> 3)) * NN + (idx & 7) * 4); } }
#define SSTSCH(bf) { \
    _Pragma("unroll") for (int it = 0; it < 8; it++) { int idx = it * 128 + t; \
        *(uint4*)&sU[bf][idx >> 5][(idx & 31) * 4] = cvt4(uf[it]); } \
    _Pragma("unroll") for (int it = 0; it < 2; it++) { int idx = it * 128 + t; \
        *(uint4*)&sC[bf][idx >> 3][(idx & 7) * 4] = cvt4(cf[it]); } }

    SLOADCH(0); SSTSCH(0); SLOADCH(32);
    __syncthreads();

    float acc[2][4][4] = {};
#pragma unroll
    for (int s = 0; s < 4; s++) {
        if (s < 3) { SSTSCH((s + 1) & 1); }
        if (s < 2) SLOADCH((s + 2) * 32);
        int bf = s & 1;
#pragma unroll
        for (int ks = 0; ks < 4; ks++) {
            int k0 = ks * 8;
            uint a[2][4];
#pragma unroll
            for (int mt = 0; mt < 2; mt++) {
                a[mt][0] = sC[bf][k0 + j4][mt * 16 + g4];
                a[mt][1] = sC[bf][k0 + j4][mt * 16 + g4 + 8];
                a[mt][2] = sC[bf][k0 + j4 + 4][mt * 16 + g4];
                a[mt][3] = sC[bf][k0 + j4 + 4][mt * 16 + g4 + 8];
            }
#pragma unroll
            for (int ct = 0; ct < 4; ct++) {
                uint b0 = sU[bf][k0 + j4][w * 32 + ct * 8 + g4];
                uint b1 = sU[bf][k0 + j4 + 4][w * 32 + ct * 8 + g4];
#pragma unroll
                for (int mt = 0; mt < 2; mt++)
                    mma_tf32(acc[mt][ct], a[mt][0], a[mt][1], a[mt][2], a[mt][3], b0, b1);
            }
        }
        __syncthreads();
    }

    // store: D[n][c], rows n = mt*16 + g4 (+8), cols c = c0g + w*32 + ct*8 + 2*j4
    float* sp = g_Spart + ((size_t)isp * BB + b) * NN * CC;
#pragma unroll
    for (int mt = 0; mt < 2; mt++)
#pragma unroll
        for (int ct = 0; ct < 4; ct++) {
            int cpos = c0g + w * 32 + ct * 8 + 2 * j4;
            int n0 = mt * 16 + g4;
            *(float2*)(sp + (size_t)n0 * CC + cpos) =
                make_float2(acc[mt][ct][0], acc[mt][ct][1]);
            *(float2*)(sp + (size_t)(n0 + 8) * CC + cpos) =
                make_float2(acc[mt][ct][2], acc[mt][ct][3]);
        }
}

// ---- caps: out = squash(S @ W_n), V = out @ W_n^T -----------------------
#define CAPS_BL 8
#define CAPS_SM ((256 * 65 + CAPS_BL * 256 + CAPS_BL * 65) * 4)
__global__ __launch_bounds__(256, 1) void k_caps(const float* __restrict__ W,
                                                 int mode, float* __restrict__ dout) {
    extern __shared__ float sm[];
    float* sW = sm;                      // [256][65]
    float* sS = sm + 256 * 65;           // [8][256]
    float* sO = sS + CAPS_BL * 256;      // [8][65]
    int n = blockIdx.x, bg = blockIdx.y;
    int t = threadIdx.x, lane = t & 31, w = t >> 5;

#pragma unroll
    for (int r = 0; r < 32; r++) {
        int c = w + 8 * r;
        const float* wp = W + (size_t)c * ND + n * DD;
        sW[c * 65 + lane] = wp[lane];
        sW[c * 65 + lane + 32] = wp[lane + 32];
    }
#pragma unroll
    for (int bl = 0; bl < CAPS_BL; bl++) {
        int b = bg * CAPS_BL + bl;
        float s = 0.f;
        if (mode == 0) {
#pragma unroll
            for (int q = 0; q < 8; q++) s += g_part[(b * 8 + q) * CC + t];
            s *= (1.0f / 32.0f);
        } else {
#pragma unroll
            for (int q = 0; q < ISP; q++)
                s += g_Spart[(((size_t)q * BB + b) * NN + n) * CC + t];
        }
        sS[bl * CC + t] = s;
    }
    __syncthreads();

    float a0 = 0.f, a1 = 0.f;
    for (int k = 0; k < CC; k++) {
        float s = sS[w * CC + k];
        a0 += s * sW[k * 65 + lane];
        a1 += s * sW[k * 65 + lane + 32];
    }
    float sq = a0 * a0 + a1 * a1;
#pragma unroll
    for (int off = 16; off; off >>= 1) sq += __shfl_xor_sync(0xffffffffu, sq, off);
    float f = rsqrtf(sq + 1e-7f);
    a0 *= f; a1 *= f;
    sO[w * 65 + lane] = a0; sO[w * 65 + lane + 32] = a1;
    if (mode == 2) {
        int b = bg * CAPS_BL + w;
        dout[(size_t)(b * NN + n) * DD + lane] = a0;
        dout[(size_t)(b * NN + n) * DD + lane + 32] = a1;
        return;
    }
    __syncthreads();

    float accB[8] = {};
    for (int k = 0; k < DD; k++) {
        float a = sO[w * 65 + k];
#pragma unroll
        for (int q = 0; q < 8; q++) accB[q] += a * sW[(lane + 32 * q) * 65 + k];
    }
    int b = bg * CAPS_BL + w;
#pragma unroll
    for (int q = 0; q < 8; q++)
        g_V[(size_t)(b * NN + n) * CC + lane + 32 * q] = accB[q];
}

// ---------------------------------------------------------------------------
extern "C" void kernel_launch(void* const* d_in, const int* in_sizes, int n_in,
                              void* d_out, int out_size) {
    const float* u = (const float*)d_in[0];
    const float* W = (const float*)d_in[1];
    if (n_in >= 2 && in_sizes[0] == CC * ND) {
        u = (const float*)d_in[1];
        W = (const float*)d_in[0];
    }
    float* out = (float*)d_out;

    cudaFuncSetAttribute(k_caps, cudaFuncAttributeMaxDynamicSharedMemorySize, CAPS_SM);

    k_colsum_part<<<dim3(8, BB), 256>>>(u);
    k_caps<<<dim3(NN, BB / CAPS_BL), 256, CAPS_SM>>>(W, 0, nullptr);

    for (int pass = 0; pass < 2; pass++) {
        k_blog<<<dim3(16, BB), 128>>>(u);
        k_sgemm<<<dim3(ISP, 2, BB), 128>>>(u);
        k_caps<<<dim3(NN, BB / CAPS_BL), 256, CAPS_SM>>>(W, pass == 0 ? 1 : 2,
                                                          pass == 0 ? nullptr : out);
    }
}

// round 11
// speedup vs baseline: 2.6175x; 1.0787x over previous
#include <cuda_runtime.h>
#include <cuda_bf16.h>
#include <cstdint>

// Capsule routing, factorized. Fused per-pass kernel: blog(tf32 mma) -> smem
// softmax -> sgemm(tf32 mma), reading each u tile ONCE. caps/colsum fp32.
// u (32,1024,256) f32; W (256,2048) f32; out (32,32,64) f32.

#define BB 32
#define II 1024
#define CC 256
#define NN 32
#define DD 64
#define ND 2048
#define ICH 16   // i-chunks of 64 -> also # of S partials

typedef unsigned int uint;

__device__ float g_part[BB * 8 * CC];            // colsum partials
__device__ float g_V[BB * NN * CC];              // V[b][n][c]
__device__ float g_Spart[ICH * BB * NN * CC];    // S partials [ich][b][n][c]

__device__ __forceinline__ uint tf32c(float f) {
    uint r; asm("cvt.rna.tf32.f32 %0, %1;" : "=r"(r) : "f"(f)); return r;
}
__device__ __forceinline__ void mma_tf32(float* d, uint a0, uint a1, uint a2, uint a3,
                                         uint b0, uint b1) {
    asm("mma.sync.aligned.m16n8k8.row.col.f32.tf32.tf32.f32 "
        "{%0,%1,%2,%3},{%4,%5,%6,%7},{%8,%9},{%0,%1,%2,%3};"
        : "+f"(d[0]), "+f"(d[1]), "+f"(d[2]), "+f"(d[3])
        : "r"(a0), "r"(a1), "r"(a2), "r"(a3), "r"(b0), "r"(b1));
}
__device__ __forceinline__ uint4 cvt4(float4 v) {
    return make_uint4(tf32c(v.x), tf32c(v.y), tf32c(v.z), tf32c(v.w));
}

// ---- colsum partials ----------------------------------------------------
__global__ void k_colsum_part(const float* __restrict__ u) {
    int q = blockIdx.x, b = blockIdx.y, c = threadIdx.x;
    const float* p = u + (size_t)b * II * CC + (size_t)q * 128 * CC + c;
    float s = 0.f;
#pragma unroll 8
    for (int i = 0; i < 128; i++) s += p[(size_t)i * CC];
    g_part[(b * 8 + q) * CC + c] = s;
}

// ---- fused routing pass -------------------------------------------------
// grid (ich=16, b=32), 256 thr.
// phase1: logits[64i x 32n] = U_chunk @ V^T  (warp w: m-tile w>>1, n-tiles (w&1)*2+{0,1})
// softmax over n in smem; phase2: Spart[32n x 256c] = coef^T @ U_chunk
//   (warp w: c-slice w*32..+32, 2 n m-tiles)
#define FSM ((96 * 260 + 64 * 36) * 4)
__global__ __launch_bounds__(256) void k_fused(const float* __restrict__ u) {
    extern __shared__ uint smraw[];
    uint (*sU)[260] = (uint(*)[260])smraw;                    // tf32 u [64i][256c]
    uint (*sV)[260] = (uint(*)[260])(smraw + 64 * 260);       // tf32 V [32n][256c]
    float (*sCf)[36] = (float(*)[36])(smraw + 96 * 260);      // logits/coef [64i][32n]

    int ich = blockIdx.x, b = blockIdx.y;
    int i0 = ich * 64;
    int t = threadIdx.x, lane = t & 31, w = t >> 5;
    int g4 = lane >> 2, j4 = lane & 3;

    // load V chunk (32x256) -> tf32 smem
#pragma unroll
    for (int it = 0; it < 8; it++) {
        int idx = it * 256 + t, row = idx >> 6, c4 = idx & 63;
        float4 v = *(const float4*)(g_V + ((size_t)b * NN + row) * CC + c4 * 4);
        *(uint4*)&sV[row][c4 * 4] = cvt4(v);
    }
    // load U chunk (64x256) -> tf32 smem
#pragma unroll
    for (int it = 0; it < 16; it++) {
        int idx = it * 256 + t, row = idx >> 6, c4 = idx & 63;
        float4 v = *(const float4*)(u + ((size_t)b * II + i0 + row) * CC + c4 * 4);
        *(uint4*)&sU[row][c4 * 4] = cvt4(v);
    }
    __syncthreads();

    // ---- phase 1: logits ----
    {
        int mt1 = w >> 1, nb = (w & 1) * 2;
        float acc1[2][4] = {};
#pragma unroll 8
        for (int ks = 0; ks < 32; ks++) {
            int k0 = ks * 8;
            uint a0 = sU[mt1 * 16 + g4][k0 + j4];
            uint a1 = sU[mt1 * 16 + g4 + 8][k0 + j4];
            uint a2 = sU[mt1 * 16 + g4][k0 + j4 + 4];
            uint a3 = sU[mt1 * 16 + g4 + 8][k0 + j4 + 4];
#pragma unroll
            for (int ntl = 0; ntl < 2; ntl++) {
                int nt = nb + ntl;
                uint b0 = sV[nt * 8 + g4][k0 + j4];
                uint b1 = sV[nt * 8 + g4][k0 + j4 + 4];
                mma_tf32(acc1[ntl], a0, a1, a2, a3, b0, b1);
            }
        }
        // raw logits -> sCf[i][n]
#pragma unroll
        for (int ntl = 0; ntl < 2; ntl++) {
            int nt = nb + ntl, ncol = nt * 8 + 2 * j4;
            *(float2*)&sCf[mt1 * 16 + g4][ncol] =
                make_float2(acc1[ntl][0], acc1[ntl][1]);
            *(float2*)&sCf[mt1 * 16 + g4 + 8][ncol] =
                make_float2(acc1[ntl][2], acc1[ntl][3]);
        }
    }
    __syncthreads();

    // ---- softmax over n (row = one i) ----
    if (t < 64) {
        float vv[NN];
        float m = -1e30f;
#pragma unroll
        for (int n = 0; n < NN; n++) { vv[n] = sCf[t][n]; m = fmaxf(m, vv[n]); }
        float s = 0.f;
#pragma unroll
        for (int n = 0; n < NN; n++) { vv[n] = __expf(vv[n] - m); s += vv[n]; }
        float inv = 1.0f / s;
#pragma unroll
        for (int n = 0; n < NN; n++) sCf[t][n] = vv[n] * inv;
    }
    __syncthreads();

    // ---- phase 2: Spart = coef^T @ U_chunk ----
    {
        float acc2[2][4][4] = {};
#pragma unroll
        for (int ks = 0; ks < 8; ks++) {
            int k0 = ks * 8;
            uint a[2][4];
#pragma unroll
            for (int mt = 0; mt < 2; mt++) {
                a[mt][0] = tf32c(sCf[k0 + j4][mt * 16 + g4]);
                a[mt][1] = tf32c(sCf[k0 + j4][mt * 16 + g4 + 8]);
                a[mt][2] = tf32c(sCf[k0 + j4 + 4][mt * 16 + g4]);
                a[mt][3] = tf32c(sCf[k0 + j4 + 4][mt * 16 + g4 + 8]);
            }
#pragma unroll
            for (int ct = 0; ct < 4; ct++) {
                int c = w * 32 + ct * 8 + g4;
                uint b0 = sU[k0 + j4][c];
                uint b1 = sU[k0 + j4 + 4][c];
#pragma unroll
                for (int mt = 0; mt < 2; mt++)
                    mma_tf32(acc2[mt][ct], a[mt][0], a[mt][1], a[mt][2], a[mt][3],
                             b0, b1);
            }
        }
        float* sp = g_Spart + ((size_t)ich * BB + b) * NN * CC;
#pragma unroll
        for (int mt = 0; mt < 2; mt++)
#pragma unroll
            for (int ct = 0; ct < 4; ct++) {
                int cpos = w * 32 + ct * 8 + 2 * j4;
                int n0 = mt * 16 + g4;
                *(float2*)(sp + (size_t)n0 * CC + cpos) =
                    make_float2(acc2[mt][ct][0], acc2[mt][ct][1]);
                *(float2*)(sp + (size_t)(n0 + 8) * CC + cpos) =
                    make_float2(acc2[mt][ct][2], acc2[mt][ct][3]);
            }
    }
}

// ---- caps: out = squash(S @ W_n), V = out @ W_n^T -----------------------
#define CAPS_BL 8
#define CAPS_SM ((256 * 65 + CAPS_BL * 256 + CAPS_BL * 65) * 4)
__global__ __launch_bounds__(256, 1) void k_caps(const float* __restrict__ W,
                                                 int mode, float* __restrict__ dout) {
    extern __shared__ float sm[];
    float* sW = sm;                      // [256][65]
    float* sS = sm + 256 * 65;           // [8][256]
    float* sO = sS + CAPS_BL * 256;      // [8][65]
    int n = blockIdx.x, bg = blockIdx.y;
    int t = threadIdx.x, lane = t & 31, w = t >> 5;

#pragma unroll
    for (int r = 0; r < 32; r++) {
        int c = w + 8 * r;
        const float* wp = W + (size_t)c * ND + n * DD;
        sW[c * 65 + lane] = wp[lane];
        sW[c * 65 + lane + 32] = wp[lane + 32];
    }
#pragma unroll
    for (int bl = 0; bl < CAPS_BL; bl++) {
        int b = bg * CAPS_BL + bl;
        float s = 0.f;
        if (mode == 0) {
#pragma unroll
            for (int q = 0; q < 8; q++) s += g_part[(b * 8 + q) * CC + t];
            s *= (1.0f / 32.0f);
        } else {
#pragma unroll
            for (int q = 0; q < ICH; q++)
                s += g_Spart[(((size_t)q * BB + b) * NN + n) * CC + t];
        }
        sS[bl * CC + t] = s;
    }
    __syncthreads();

    float a0 = 0.f, a1 = 0.f;
    for (int k = 0; k < CC; k++) {
        float s = sS[w * CC + k];
        a0 += s * sW[k * 65 + lane];
        a1 += s * sW[k * 65 + lane + 32];
    }
    float sq = a0 * a0 + a1 * a1;
#pragma unroll
    for (int off = 16; off; off >>= 1) sq += __shfl_xor_sync(0xffffffffu, sq, off);
    float f = rsqrtf(sq + 1e-7f);
    a0 *= f; a1 *= f;
    sO[w * 65 + lane] = a0; sO[w * 65 + lane + 32] = a1;
    if (mode == 2) {
        int b = bg * CAPS_BL + w;
        dout[(size_t)(b * NN + n) * DD + lane] = a0;
        dout[(size_t)(b * NN + n) * DD + lane + 32] = a1;
        return;
    }
    __syncthreads();

    float accB[8] = {};
    for (int k = 0; k < DD; k++) {
        float a = sO[w * 65 + k];
#pragma unroll
        for (int q = 0; q < 8; q++) accB[q] += a * sW[(lane + 32 * q) * 65 + k];
    }
    int b = bg * CAPS_BL + w;
#pragma unroll
    for (int q = 0; q < 8; q++)
        g_V[(size_t)(b * NN + n) * CC + lane + 32 * q] = accB[q];
}

// ---------------------------------------------------------------------------
extern "C" void kernel_launch(void* const* d_in, const int* in_sizes, int n_in,
                              void* d_out, int out_size) {
    const float* u = (const float*)d_in[0];
    const float* W = (const float*)d_in[1];
    if (n_in >= 2 && in_sizes[0] == CC * ND) {
        u = (const float*)d_in[1];
        W = (const float*)d_in[0];
    }
    float* out = (float*)d_out;

    cudaFuncSetAttribute(k_caps, cudaFuncAttributeMaxDynamicSharedMemorySize, CAPS_SM);
    cudaFuncSetAttribute(k_fused, cudaFuncAttributeMaxDynamicSharedMemorySize, FSM);

    k_colsum_part<<<dim3(8, BB), 256>>>(u);
    k_caps<<<dim3(NN, BB / CAPS_BL), 256, CAPS_SM>>>(W, 0, nullptr);

    for (int pass = 0; pass < 2; pass++) {
        k_fused<<<dim3(ICH, BB), 256, FSM>>>(u);
        k_caps<<<dim3(NN, BB / CAPS_BL), 256, CAPS_SM>>>(W, pass == 0 ? 1 : 2,
                                                          pass == 0 ? nullptr : out);
    }
}